// round 11
// baseline (speedup 1.0000x reference)
#include <cuda_runtime.h>
#include <cuda_fp16.h>

#define B_ 8
#define H_ 64
#define W_ 64
#define C_ 256
#define N_ 512
#define POOL_ 7
#define NPOS (POOL_ * POOL_)   // 49
#define NBOX (B_ * N_)         // 4096
#define FM_ELEMS (B_ * H_ * W_ * C_)   // 8388608

// fp16 copy of the feature map (16.8 MB static scratch — no allocation).
__device__ __half g_fmh[FM_ELEMS];

__global__ void __launch_bounds__(256) fm_convert_kernel(const float* __restrict__ fm) {
    const int i = blockIdx.x * blockDim.x + threadIdx.x;   // over FM_ELEMS/4
    const float4 v = __ldg((const float4*)fm + i);
    const __half2 h01 = __floats2half2_rn(v.x, v.y);
    const __half2 h23 = __floats2half2_rn(v.z, v.w);
    uint2 u;
    u.x = *(const unsigned int*)&h01;
    u.y = *(const unsigned int*)&h23;
    ((uint2*)g_fmh)[i] = u;
}

__global__ void __launch_bounds__(224, 6) roi_align_fused(const float* __restrict__ boxes,
                                                          float* __restrict__ out) {
    __shared__ int4   s_off[NPOS];
    __shared__ float4 s_w[NPOS];

    const int box = blockIdx.x;                         // 0..4095
    const int tid = threadIdx.y * 32 + threadIdx.x;     // 0..223

    if (tid < NPOS) {
        const int b  = box >> 9;
        const int py = tid / POOL_;
        const int px = tid - py * POOL_;

        const float4 bx = __ldg((const float4*)(boxes + (size_t)box * 4));
        const float x1 = bx.x, y1 = bx.y, x2 = bx.z, y2 = bx.w;

        const float ys = y1 * (H_ - 1) + (float)py * ((y2 - y1) * (H_ - 1) / (POOL_ - 1));
        const float xs = x1 * (W_ - 1) + (float)px * ((x2 - x1) * (W_ - 1) / (POOL_ - 1));

        const float yf = floorf(ys);
        const float xf = floorf(xs);
        const float fy = ys - yf;
        const float fx = xs - xf;

        int yt = (int)yf, xl = (int)xf;
        int yb = yt + 1,  xr = xl + 1;
        yt = min(max(yt, 0), H_ - 1);
        yb = min(max(yb, 0), H_ - 1);
        xl = min(max(xl, 0), W_ - 1);
        xr = min(max(xr, 0), W_ - 1);

        // normalized boxes in [0,1] => samples always in-range; mask always true.
        s_w[tid] = make_float4((1.f - fy) * (1.f - fx),
                               (1.f - fy) * fx,
                               fy * (1.f - fx),
                               fy * fx);

        const int base = b * (H_ * W_ * C_);
        s_off[tid] = make_int4(base + (yt * W_ + xl) * C_,
                               base + (yt * W_ + xr) * C_,
                               base + (yb * W_ + xl) * C_,
                               base + (yb * W_ + xr) * C_);
    }
    __syncthreads();

    const int c = threadIdx.x * 8;                      // 32 lanes x 8 fp16 channels = 256
    float* obase = out + (size_t)box * NPOS * C_ + c;

    #pragma unroll
    for (int py = 0; py < POOL_; py++) {
        const int pos = py * POOL_ + threadIdx.y;       // one warp per pool row

        const int4   offs = s_off[pos];
        const float4 w    = s_w[pos];

        // 8 channels per lane: one LDG.128 per corner, 4 independent in flight
        const uint4 utl = __ldg((const uint4*)(g_fmh + offs.x + c));
        const uint4 utr = __ldg((const uint4*)(g_fmh + offs.y + c));
        const uint4 ubl = __ldg((const uint4*)(g_fmh + offs.z + c));
        const uint4 ubr = __ldg((const uint4*)(g_fmh + offs.w + c));

        const __half2* tlh = (const __half2*)&utl;
        const __half2* trh = (const __half2*)&utr;
        const __half2* blh = (const __half2*)&ubl;
        const __half2* brh = (const __half2*)&ubr;

        float o[8];
        #pragma unroll
        for (int j = 0; j < 4; j++) {
            const float2 tl = __half22float2(tlh[j]);
            const float2 tr = __half22float2(trh[j]);
            const float2 bl = __half22float2(blh[j]);
            const float2 br = __half22float2(brh[j]);
            o[2 * j + 0] = fmaf(br.x, w.w, fmaf(bl.x, w.z, fmaf(tr.x, w.y, tl.x * w.x)));
            o[2 * j + 1] = fmaf(br.y, w.w, fmaf(bl.y, w.z, fmaf(tr.y, w.y, tl.y * w.x)));
        }

        float* dst = obase + (size_t)pos * C_;
        __stcs((float4*)dst,     make_float4(o[0], o[1], o[2], o[3]));
        __stcs((float4*)dst + 1, make_float4(o[4], o[5], o[6], o[7]));
    }
}

extern "C" void kernel_launch(void* const* d_in, const int* in_sizes, int n_in,
                              void* d_out, int out_size) {
    const float* fm    = (const float*)d_in[0];   // [8,64,64,256] fp32
    const float* boxes = (const float*)d_in[1];   // [8,512,4]
    float* out = (float*)d_out;                   // [8,512,7,7,256] fp32

    // 1) fp32 -> fp16 feature-map copy
    fm_convert_kernel<<<FM_ELEMS / 4 / 256, 256>>>(fm);

    // 2) gather + bilinear blend from fp16 copy
    dim3 block(32, POOL_);      // 224 threads, one warp per pool row
    roi_align_fused<<<NBOX, block>>>(boxes, out);
}

// round 12
// speedup vs baseline: 1.5754x; 1.5754x over previous
#include <cuda_runtime.h>
#include <cuda_fp16.h>

#define B_ 8
#define H_ 64
#define W_ 64
#define C_ 256
#define N_ 512
#define POOL_ 7
#define NPOS (POOL_ * POOL_)   // 49
#define NBOX (B_ * N_)         // 4096
#define FM_ELEMS (B_ * H_ * W_ * C_)   // 8388608

// fp16 copy of the feature map (16.8 MB static scratch — no allocation).
__device__ __half g_fmh[FM_ELEMS];

__global__ void __launch_bounds__(256) fm_convert_kernel(const float* __restrict__ fm) {
    const int i = blockIdx.x * blockDim.x + threadIdx.x;   // over FM_ELEMS/4
    const float4 v = __ldg((const float4*)fm + i);
    const __half2 h01 = __floats2half2_rn(v.x, v.y);
    const __half2 h23 = __floats2half2_rn(v.z, v.w);
    uint2 u;
    u.x = *(const unsigned int*)&h01;
    u.y = *(const unsigned int*)&h23;
    ((uint2*)g_fmh)[i] = u;
}

__device__ __forceinline__ float4 blend4(uint2 utl, uint2 utr, uint2 ubl, uint2 ubr, float4 w) {
    const float2 tl01 = __half22float2(*(const __half2*)&utl.x);
    const float2 tl23 = __half22float2(*(const __half2*)&utl.y);
    const float2 tr01 = __half22float2(*(const __half2*)&utr.x);
    const float2 tr23 = __half22float2(*(const __half2*)&utr.y);
    const float2 bl01 = __half22float2(*(const __half2*)&ubl.x);
    const float2 bl23 = __half22float2(*(const __half2*)&ubl.y);
    const float2 br01 = __half22float2(*(const __half2*)&ubr.x);
    const float2 br23 = __half22float2(*(const __half2*)&ubr.y);
    float4 o;
    o.x = fmaf(br01.x, w.w, fmaf(bl01.x, w.z, fmaf(tr01.x, w.y, tl01.x * w.x)));
    o.y = fmaf(br01.y, w.w, fmaf(bl01.y, w.z, fmaf(tr01.y, w.y, tl01.y * w.x)));
    o.z = fmaf(br23.x, w.w, fmaf(bl23.x, w.z, fmaf(tr23.x, w.y, tl23.x * w.x)));
    o.w = fmaf(br23.y, w.w, fmaf(bl23.y, w.z, fmaf(tr23.y, w.y, tl23.y * w.x)));
    return o;
}

__global__ void __launch_bounds__(448) roi_align_fused(const float* __restrict__ boxes,
                                                       float* __restrict__ out) {
    __shared__ int4   s_off[NPOS];
    __shared__ float4 s_w[NPOS];

    const int box = blockIdx.x;                         // 0..4095
    const int tid = threadIdx.y * 64 + threadIdx.x;

    if (tid < NPOS) {
        const int b  = box >> 9;
        const int py = tid / POOL_;
        const int px = tid - py * POOL_;

        const float4 bx = __ldg((const float4*)(boxes + (size_t)box * 4));
        const float x1 = bx.x, y1 = bx.y, x2 = bx.z, y2 = bx.w;

        const float ys = y1 * (H_ - 1) + (float)py * ((y2 - y1) * (H_ - 1) / (POOL_ - 1));
        const float xs = x1 * (W_ - 1) + (float)px * ((x2 - x1) * (W_ - 1) / (POOL_ - 1));

        const float yf = floorf(ys);
        const float xf = floorf(xs);
        const float fy = ys - yf;
        const float fx = xs - xf;

        int yt = (int)yf, xl = (int)xf;
        int yb = yt + 1,  xr = xl + 1;
        yt = min(max(yt, 0), H_ - 1);
        yb = min(max(yb, 0), H_ - 1);
        xl = min(max(xl, 0), W_ - 1);
        xr = min(max(xr, 0), W_ - 1);

        // normalized boxes in [0,1] => samples always in-range; mask always true.
        s_w[tid] = make_float4((1.f - fy) * (1.f - fx),
                               (1.f - fy) * fx,
                               fy * (1.f - fx),
                               fy * fx);

        const int base = b * (H_ * W_ * C_);
        s_off[tid] = make_int4(base + (yt * W_ + xl) * C_,
                               base + (yt * W_ + xr) * C_,
                               base + (yb * W_ + xl) * C_,
                               base + (yb * W_ + xr) * C_);
    }
    __syncthreads();

    const int lane4 = threadIdx.x;                      // 64 lanes x 4 channels
    float* obase = out + (size_t)box * NPOS * C_ + lane4 * 4;

    // 7 rows: 3 paired iterations (rows k and k+4) + 1 single (row 3).
    #pragma unroll
    for (int k = 0; k < 3; k++) {
        const int posA = k * POOL_ + threadIdx.y;             // rows 0,1,2
        const int posB = (k + 4) * POOL_ + threadIdx.y;       // rows 4,5,6

        const int4 offA = s_off[posA];
        const int4 offB = s_off[posB];

        // 8 independent LDG.64 in flight per thread
        const uint2 atl = __ldg((const uint2*)(g_fmh + offA.x) + lane4);
        const uint2 atr = __ldg((const uint2*)(g_fmh + offA.y) + lane4);
        const uint2 abl = __ldg((const uint2*)(g_fmh + offA.z) + lane4);
        const uint2 abr = __ldg((const uint2*)(g_fmh + offA.w) + lane4);
        const uint2 btl = __ldg((const uint2*)(g_fmh + offB.x) + lane4);
        const uint2 btr = __ldg((const uint2*)(g_fmh + offB.y) + lane4);
        const uint2 bbl = __ldg((const uint2*)(g_fmh + offB.z) + lane4);
        const uint2 bbr = __ldg((const uint2*)(g_fmh + offB.w) + lane4);

        const float4 oA = blend4(atl, atr, abl, abr, s_w[posA]);
        const float4 oB = blend4(btl, btr, bbl, bbr, s_w[posB]);

        __stcs((float4*)(obase + (size_t)posA * C_), oA);
        __stcs((float4*)(obase + (size_t)posB * C_), oB);
    }
    {
        const int pos = 3 * POOL_ + threadIdx.y;              // row 3
        const int4 offs = s_off[pos];
        const uint2 tl = __ldg((const uint2*)(g_fmh + offs.x) + lane4);
        const uint2 tr = __ldg((const uint2*)(g_fmh + offs.y) + lane4);
        const uint2 bl = __ldg((const uint2*)(g_fmh + offs.z) + lane4);
        const uint2 br = __ldg((const uint2*)(g_fmh + offs.w) + lane4);
        const float4 o = blend4(tl, tr, bl, br, s_w[pos]);
        __stcs((float4*)(obase + (size_t)pos * C_), o);
    }
}

extern "C" void kernel_launch(void* const* d_in, const int* in_sizes, int n_in,
                              void* d_out, int out_size) {
    const float* fm    = (const float*)d_in[0];   // [8,64,64,256] fp32
    const float* boxes = (const float*)d_in[1];   // [8,512,4]
    float* out = (float*)d_out;                   // [8,512,7,7,256] fp32

    // 1) fp32 -> fp16 feature-map copy
    fm_convert_kernel<<<FM_ELEMS / 4 / 256, 256>>>(fm);

    // 2) gather + bilinear blend from fp16 copy, 2 positions in flight per thread
    dim3 block(64, POOL_);      // 448 threads
    roi_align_fused<<<NBOX, block>>>(boxes, out);
}

// round 13
// speedup vs baseline: 1.5807x; 1.0034x over previous
#include <cuda_runtime.h>
#include <cuda_fp16.h>

#define B_ 8
#define H_ 64
#define W_ 64
#define C_ 256
#define N_ 512
#define POOL_ 7
#define NPOS (POOL_ * POOL_)   // 49
#define NBOX (B_ * N_)         // 4096
#define FM_ELEMS (B_ * H_ * W_ * C_)   // 8388608

// fp16 copy of the feature map (16.8 MB static scratch — no allocation).
__device__ __half g_fmh[FM_ELEMS];

__global__ void __launch_bounds__(256) fm_convert_kernel(const float* __restrict__ fm) {
    const int i = blockIdx.x * blockDim.x + threadIdx.x;   // over FM_ELEMS/4
    const float4 v = __ldg((const float4*)fm + i);
    const __half2 h01 = __floats2half2_rn(v.x, v.y);
    const __half2 h23 = __floats2half2_rn(v.z, v.w);
    uint2 u;
    u.x = *(const unsigned int*)&h01;
    u.y = *(const unsigned int*)&h23;
    ((uint2*)g_fmh)[i] = u;
}

__device__ __forceinline__ float4 blend4(uint2 utl, uint2 utr, uint2 ubl, uint2 ubr, float4 w) {
    const float2 tl01 = __half22float2(*(const __half2*)&utl.x);
    const float2 tl23 = __half22float2(*(const __half2*)&utl.y);
    const float2 tr01 = __half22float2(*(const __half2*)&utr.x);
    const float2 tr23 = __half22float2(*(const __half2*)&utr.y);
    const float2 bl01 = __half22float2(*(const __half2*)&ubl.x);
    const float2 bl23 = __half22float2(*(const __half2*)&ubl.y);
    const float2 br01 = __half22float2(*(const __half2*)&ubr.x);
    const float2 br23 = __half22float2(*(const __half2*)&ubr.y);
    float4 o;
    o.x = fmaf(br01.x, w.w, fmaf(bl01.x, w.z, fmaf(tr01.x, w.y, tl01.x * w.x)));
    o.y = fmaf(br01.y, w.w, fmaf(bl01.y, w.z, fmaf(tr01.y, w.y, tl01.y * w.x)));
    o.z = fmaf(br23.x, w.w, fmaf(bl23.x, w.z, fmaf(tr23.x, w.y, tl23.x * w.x)));
    o.w = fmaf(br23.y, w.w, fmaf(bl23.y, w.z, fmaf(tr23.y, w.y, tl23.y * w.x)));
    return o;
}

__global__ void __launch_bounds__(448) roi_align_fused(const float* __restrict__ boxes,
                                                       float* __restrict__ out) {
    __shared__ int4   s_off[NPOS];
    __shared__ float4 s_w[NPOS];

    const int box = blockIdx.x;                         // 0..4095
    const int tid = threadIdx.y * 64 + threadIdx.x;

    if (tid < NPOS) {
        const int b  = box >> 9;
        const int py = tid / POOL_;
        const int px = tid - py * POOL_;

        const float4 bx = __ldg((const float4*)(boxes + (size_t)box * 4));
        const float x1 = bx.x, y1 = bx.y, x2 = bx.z, y2 = bx.w;

        const float ys = y1 * (H_ - 1) + (float)py * ((y2 - y1) * (H_ - 1) / (POOL_ - 1));
        const float xs = x1 * (W_ - 1) + (float)px * ((x2 - x1) * (W_ - 1) / (POOL_ - 1));

        const float yf = floorf(ys);
        const float xf = floorf(xs);
        const float fy = ys - yf;
        const float fx = xs - xf;

        int yt = (int)yf, xl = (int)xf;
        int yb = yt + 1,  xr = xl + 1;
        yt = min(max(yt, 0), H_ - 1);
        yb = min(max(yb, 0), H_ - 1);
        xl = min(max(xl, 0), W_ - 1);
        xr = min(max(xr, 0), W_ - 1);

        // normalized boxes in [0,1] => samples always in-range; mask always true.
        s_w[tid] = make_float4((1.f - fy) * (1.f - fx),
                               (1.f - fy) * fx,
                               fy * (1.f - fx),
                               fy * fx);

        const int base = b * (H_ * W_ * C_);
        s_off[tid] = make_int4(base + (yt * W_ + xl) * C_,
                               base + (yt * W_ + xr) * C_,
                               base + (yb * W_ + xl) * C_,
                               base + (yb * W_ + xr) * C_);
    }
    __syncthreads();

    const int lane4 = threadIdx.x;                      // 64 lanes x 4 channels
    float* obase = out + (size_t)box * NPOS * C_ + lane4 * 4;

    // Group 1: rows 0-3 (16 independent LDG.64 in flight per thread)
    {
        uint2 ld[16];
        int   ps[4];
        #pragma unroll
        for (int r = 0; r < 4; r++) {
            const int pos = r * POOL_ + threadIdx.y;
            ps[r] = pos;
            const int4 offs = s_off[pos];
            ld[4 * r + 0] = __ldg((const uint2*)(g_fmh + offs.x) + lane4);
            ld[4 * r + 1] = __ldg((const uint2*)(g_fmh + offs.y) + lane4);
            ld[4 * r + 2] = __ldg((const uint2*)(g_fmh + offs.z) + lane4);
            ld[4 * r + 3] = __ldg((const uint2*)(g_fmh + offs.w) + lane4);
        }
        #pragma unroll
        for (int r = 0; r < 4; r++) {
            const float4 o = blend4(ld[4 * r], ld[4 * r + 1], ld[4 * r + 2], ld[4 * r + 3],
                                    s_w[ps[r]]);
            __stcs((float4*)(obase + (size_t)ps[r] * C_), o);
        }
    }
    // Group 2: rows 4-6 (12 loads in flight)
    {
        uint2 ld[12];
        int   ps[3];
        #pragma unroll
        for (int r = 0; r < 3; r++) {
            const int pos = (r + 4) * POOL_ + threadIdx.y;
            ps[r] = pos;
            const int4 offs = s_off[pos];
            ld[4 * r + 0] = __ldg((const uint2*)(g_fmh + offs.x) + lane4);
            ld[4 * r + 1] = __ldg((const uint2*)(g_fmh + offs.y) + lane4);
            ld[4 * r + 2] = __ldg((const uint2*)(g_fmh + offs.z) + lane4);
            ld[4 * r + 3] = __ldg((const uint2*)(g_fmh + offs.w) + lane4);
        }
        #pragma unroll
        for (int r = 0; r < 3; r++) {
            const float4 o = blend4(ld[4 * r], ld[4 * r + 1], ld[4 * r + 2], ld[4 * r + 3],
                                    s_w[ps[r]]);
            __stcs((float4*)(obase + (size_t)ps[r] * C_), o);
        }
    }
}

extern "C" void kernel_launch(void* const* d_in, const int* in_sizes, int n_in,
                              void* d_out, int out_size) {
    const float* fm    = (const float*)d_in[0];   // [8,64,64,256] fp32
    const float* boxes = (const float*)d_in[1];   // [8,512,4]
    float* out = (float*)d_out;                   // [8,512,7,7,256] fp32

    // 1) fp32 -> fp16 feature-map copy (~6 us, HBM-floor bound)
    fm_convert_kernel<<<FM_ELEMS / 4 / 256, 256>>>(fm);

    // 2) gather + bilinear blend from fp16 copy, 4 positions in flight per thread
    dim3 block(64, POOL_);      // 448 threads
    roi_align_fused<<<NBOX, block>>>(boxes, out);
}